// round 2
// baseline (speedup 1.0000x reference)
#include <cuda_runtime.h>
#include <math.h>

#define N_NODES 50000
#define N_EDGES 800000
#define D 256
#define NG 512
#define NC 10
#define LN_EPS 1e-5f

// Scratch (device globals; no allocation allowed)
__device__ float g_A[N_NODES * D];   // ping
__device__ float g_B[N_NODES * D];   // pong
__device__ float g_deg[N_NODES];
__device__ float g_dinv[N_NODES];
__device__ float g_pool[NG * D];
__device__ float g_cnt[NG];

// ---------------- degree / norm ----------------
__global__ void deg_init_kernel(float* deg) {
    int i = blockIdx.x * blockDim.x + threadIdx.x;
    if (i < N_NODES) deg[i] = 1.0f;  // self-loop
}

__global__ void deg_count_kernel(const int* __restrict__ dst, float* deg) {
    int e = blockIdx.x * blockDim.x + threadIdx.x;
    if (e < N_EDGES) atomicAdd(&deg[dst[e]], 1.0f);
}

__global__ void dinv_kernel(const float* __restrict__ deg, float* dinv) {
    int i = blockIdx.x * blockDim.x + threadIdx.x;
    if (i < N_NODES) dinv[i] = rsqrtf(deg[i]);
}

// ---------------- SGEMM: C[M,256] = A[M,256] @ W[256,256] ----------------
// 64x64 block tile, BK=16, 256 threads, 4x4 per-thread micro-tile.
__global__ void sgemm_kernel(const float* __restrict__ A,
                             const float* __restrict__ W,
                             float* __restrict__ C) {
    __shared__ float As[16][65];   // [k][m], padded
    __shared__ float Ws[16][68];   // [k][n], padded (float4-aligned rows)

    int tid = threadIdx.x;
    int bm = blockIdx.y * 64;
    int bn = blockIdx.x * 64;
    int tx = tid & 15;
    int ty = tid >> 4;

    // A-load mapping: 64 rows x 16 k, float4 along k
    int lm  = tid >> 2;          // 0..63
    int lk4 = (tid & 3) * 4;     // 0,4,8,12
    // W-load mapping: 16 k x 64 n, float4 along n
    int wk  = tid >> 4;          // 0..15
    int wn4 = (tid & 15) * 4;    // 0..60

    int gm = bm + lm;
    bool mval = (gm < N_NODES);
    const float* Arow = A + (size_t)gm * D;

    float acc[4][4];
#pragma unroll
    for (int i = 0; i < 4; i++)
#pragma unroll
        for (int j = 0; j < 4; j++) acc[i][j] = 0.0f;

    for (int k0 = 0; k0 < D; k0 += 16) {
        float4 av = mval ? *(const float4*)(Arow + k0 + lk4)
                         : make_float4(0.f, 0.f, 0.f, 0.f);
        As[lk4 + 0][lm] = av.x;
        As[lk4 + 1][lm] = av.y;
        As[lk4 + 2][lm] = av.z;
        As[lk4 + 3][lm] = av.w;

        float4 wv = *(const float4*)(W + (size_t)(k0 + wk) * D + bn + wn4);
        *(float4*)&Ws[wk][wn4] = wv;

        __syncthreads();
#pragma unroll
        for (int k = 0; k < 16; k++) {
            float a0 = As[k][ty * 4 + 0];
            float a1 = As[k][ty * 4 + 1];
            float a2 = As[k][ty * 4 + 2];
            float a3 = As[k][ty * 4 + 3];
            float4 b4 = *(const float4*)&Ws[k][tx * 4];
            acc[0][0] += a0 * b4.x; acc[0][1] += a0 * b4.y; acc[0][2] += a0 * b4.z; acc[0][3] += a0 * b4.w;
            acc[1][0] += a1 * b4.x; acc[1][1] += a1 * b4.y; acc[1][2] += a1 * b4.z; acc[1][3] += a1 * b4.w;
            acc[2][0] += a2 * b4.x; acc[2][1] += a2 * b4.y; acc[2][2] += a2 * b4.z; acc[2][3] += a2 * b4.w;
            acc[3][0] += a3 * b4.x; acc[3][1] += a3 * b4.y; acc[3][2] += a3 * b4.z; acc[3][3] += a3 * b4.w;
        }
        __syncthreads();
    }

#pragma unroll
    for (int i = 0; i < 4; i++) {
        int r = bm + ty * 4 + i;
        if (r < N_NODES) {
            float4 v = make_float4(acc[i][0], acc[i][1], acc[i][2], acc[i][3]);
            *(float4*)(C + (size_t)r * D + bn + tx * 4) = v;
        }
    }
}

// ---------------- aggregation ----------------
// init: agg[i] = h[i] * dinv[i]^2  (self-loop contribution)
__global__ void agg_init_kernel(const float* __restrict__ h,
                                const float* __restrict__ dinv,
                                float* __restrict__ agg) {
    int idx = blockIdx.x * blockDim.x + threadIdx.x;   // over N*D/4
    if (idx < N_NODES * (D / 4)) {
        int node = idx / (D / 4);
        float s = dinv[node];
        s = s * s;
        float4 v = ((const float4*)h)[idx];
        v.x *= s; v.y *= s; v.z *= s; v.w *= s;
        ((float4*)agg)[idx] = v;
    }
}

// edges: agg[dst] += h[src] * dinv[src]*dinv[dst]
__global__ void agg_edge_kernel(const int* __restrict__ src,
                                const int* __restrict__ dst,
                                const float* __restrict__ dinv,
                                const float* __restrict__ h,
                                float* __restrict__ agg) {
    int idx = blockIdx.x * blockDim.x + threadIdx.x;   // over E * (D/4)
    int e = idx >> 6;          // /64 chunks
    int c = idx & 63;
    if (e < N_EDGES) {
        int s = src[e];
        int d = dst[e];
        float w = dinv[s] * dinv[d];
        float4 v = ((const float4*)h)[s * (D / 4) + c];
        float* ap = agg + (size_t)d * D + c * 4;
        atomicAdd(ap + 0, v.x * w);
        atomicAdd(ap + 1, v.y * w);
        atomicAdd(ap + 2, v.z * w);
        atomicAdd(ap + 3, v.w * w);
    }
}

// ---------------- LayerNorm(agg + bias) + ReLU ----------------
// one warp per row, 8 rows per 256-thread block
__global__ void ln_relu_kernel(const float* __restrict__ in,
                               const float* __restrict__ bias,
                               const float* __restrict__ lw,
                               const float* __restrict__ lb,
                               float* __restrict__ out) {
    int row = blockIdx.x * 8 + (threadIdx.x >> 5);
    int lane = threadIdx.x & 31;
    if (row >= N_NODES) return;

    const float4* p  = (const float4*)(in + (size_t)row * D);
    const float4* bp = (const float4*)bias;
    float4 v0 = p[lane];       float4 v1 = p[lane + 32];
    float4 b0 = bp[lane];      float4 b1 = bp[lane + 32];
    v0.x += b0.x; v0.y += b0.y; v0.z += b0.z; v0.w += b0.w;
    v1.x += b1.x; v1.y += b1.y; v1.z += b1.z; v1.w += b1.w;

    float s = v0.x + v0.y + v0.z + v0.w + v1.x + v1.y + v1.z + v1.w;
#pragma unroll
    for (int o = 16; o > 0; o >>= 1) s += __shfl_xor_sync(0xffffffffu, s, o);
    float mu = s * (1.0f / D);

    v0.x -= mu; v0.y -= mu; v0.z -= mu; v0.w -= mu;
    v1.x -= mu; v1.y -= mu; v1.z -= mu; v1.w -= mu;
    float q = v0.x*v0.x + v0.y*v0.y + v0.z*v0.z + v0.w*v0.w
            + v1.x*v1.x + v1.y*v1.y + v1.z*v1.z + v1.w*v1.w;
#pragma unroll
    for (int o = 16; o > 0; o >>= 1) q += __shfl_xor_sync(0xffffffffu, q, o);
    float inv = rsqrtf(q * (1.0f / D) + LN_EPS);

    const float4* wp = (const float4*)lw;
    const float4* lp = (const float4*)lb;
    float4 w0 = wp[lane], w1 = wp[lane + 32];
    float4 l0 = lp[lane], l1 = lp[lane + 32];

    float4 o0, o1;
    o0.x = fmaxf(v0.x * inv * w0.x + l0.x, 0.f);
    o0.y = fmaxf(v0.y * inv * w0.y + l0.y, 0.f);
    o0.z = fmaxf(v0.z * inv * w0.z + l0.z, 0.f);
    o0.w = fmaxf(v0.w * inv * w0.w + l0.w, 0.f);
    o1.x = fmaxf(v1.x * inv * w1.x + l1.x, 0.f);
    o1.y = fmaxf(v1.y * inv * w1.y + l1.y, 0.f);
    o1.z = fmaxf(v1.z * inv * w1.z + l1.z, 0.f);
    o1.w = fmaxf(v1.w * inv * w1.w + l1.w, 0.f);

    float4* op = (float4*)(out + (size_t)row * D);
    op[lane] = o0;
    op[lane + 32] = o1;
}

// ---------------- pooling + head ----------------
__global__ void pool_zero_kernel(float* pool, float* cnt) {
    int i = blockIdx.x * blockDim.x + threadIdx.x;
    if (i < NG * D) pool[i] = 0.0f;
    if (i < NG) cnt[i] = 0.0f;
}

__global__ void pool_acc_kernel(const int* __restrict__ batch,
                                const float* __restrict__ h,
                                float* pool, float* cnt) {
    int n = blockIdx.x;
    int c = threadIdx.x;
    int g = batch[n];
    atomicAdd(&pool[g * D + c], h[(size_t)n * D + c]);
    if (c == 0) atomicAdd(&cnt[g], 1.0f);
}

__global__ void head_kernel(const float* __restrict__ pool,
                            const float* __restrict__ cnt,
                            const float* __restrict__ linW,
                            const float* __restrict__ linb,
                            float* __restrict__ out) {
    __shared__ float row[D];
    int g = blockIdx.x;
    float c = cnt[g];
    float inv = 1.0f / fmaxf(c, 1.0f);
    row[threadIdx.x] = pool[g * D + threadIdx.x] * inv;
    __syncthreads();
    if (threadIdx.x < NC) {
        float acc = linb[threadIdx.x];
#pragma unroll 8
        for (int k = 0; k < D; k++) acc += row[k] * linW[k * NC + threadIdx.x];
        out[g * NC + threadIdx.x] = acc;
    }
}

// ---------------- launch ----------------
extern "C" void kernel_launch(void* const* d_in, const int* in_sizes, int n_in,
                              void* d_out, int out_size) {
    const float* x     = (const float*)d_in[0];
    const int*   ei    = (const int*)d_in[1];   // [2, E]
    const int*   batch = (const int*)d_in[2];
    const float* W1    = (const float*)d_in[3];
    const float* b1    = (const float*)d_in[4];
    const float* W2    = (const float*)d_in[5];
    const float* b2    = (const float*)d_in[6];
    const float* ln1w  = (const float*)d_in[7];
    const float* ln1b  = (const float*)d_in[8];
    const float* ln2w  = (const float*)d_in[9];
    const float* ln2b  = (const float*)d_in[10];
    const float* linW  = (const float*)d_in[11];
    const float* linb  = (const float*)d_in[12];
    float* out = (float*)d_out;

    const int* src = ei;
    const int* dst = ei + N_EDGES;

    float *A, *B, *deg, *dinv, *pool, *cnt;
    cudaGetSymbolAddress((void**)&A,    g_A);
    cudaGetSymbolAddress((void**)&B,    g_B);
    cudaGetSymbolAddress((void**)&deg,  g_deg);
    cudaGetSymbolAddress((void**)&dinv, g_dinv);
    cudaGetSymbolAddress((void**)&pool, g_pool);
    cudaGetSymbolAddress((void**)&cnt,  g_cnt);

    // degree + normalization
    deg_init_kernel<<<(N_NODES + 255) / 256, 256>>>(deg);
    deg_count_kernel<<<(N_EDGES + 255) / 256, 256>>>(dst, deg);
    dinv_kernel<<<(N_NODES + 255) / 256, 256>>>(deg, dinv);

    dim3 ggrid(D / 64, (N_NODES + 63) / 64);
    int nchunks = N_NODES * (D / 4);
    int echunks = N_EDGES * (D / 4);

    // layer 1
    sgemm_kernel<<<ggrid, 256>>>(x, W1, A);
    agg_init_kernel<<<(nchunks + 255) / 256, 256>>>(A, dinv, B);
    agg_edge_kernel<<<(echunks + 255) / 256, 256>>>(src, dst, dinv, A, B);
    ln_relu_kernel<<<(N_NODES + 7) / 8, 256>>>(B, b1, ln1w, ln1b, A);

    // layer 2
    sgemm_kernel<<<ggrid, 256>>>(A, W2, B);
    agg_init_kernel<<<(nchunks + 255) / 256, 256>>>(B, dinv, A);
    agg_edge_kernel<<<(echunks + 255) / 256, 256>>>(src, dst, dinv, B, A);
    ln_relu_kernel<<<(N_NODES + 7) / 8, 256>>>(A, b2, ln2w, ln2b, B);

    // pool + head
    pool_zero_kernel<<<(NG * D + 255) / 256, 256>>>(pool, cnt);
    pool_acc_kernel<<<N_NODES, 256>>>(batch, B, pool, cnt);
    head_kernel<<<NG, D>>>(pool, cnt, linW, linb, out);
}

// round 3
// speedup vs baseline: 2.4693x; 2.4693x over previous
#include <cuda_runtime.h>
#include <math.h>

#define N_NODES 50000
#define N_EDGES 800000
#define D 256
#define NG 512
#define NC 10
#define LN_EPS 1e-5f

// Scratch (device globals; no allocation allowed)
__device__ float g_A[N_NODES * D];   // ping
__device__ float g_B[N_NODES * D];   // pong
__device__ float g_dinv[N_NODES];
__device__ int   g_counts[N_NODES];
__device__ int   g_offsets[N_NODES + 1];
__device__ int   g_cursor[N_NODES];
__device__ int   g_csr_src[N_EDGES];
__device__ float g_csr_w[N_EDGES];

// ---------------- degree / norm ----------------
__global__ void count_zero_kernel(int* counts) {
    int i = blockIdx.x * blockDim.x + threadIdx.x;
    if (i < N_NODES) counts[i] = 0;
}

__global__ void deg_count_kernel(const int* __restrict__ dst, int* counts) {
    int e = blockIdx.x * blockDim.x + threadIdx.x;
    if (e < N_EDGES) atomicAdd(&counts[dst[e]], 1);
}

__global__ void dinv_kernel(const int* __restrict__ counts, float* dinv) {
    int i = blockIdx.x * blockDim.x + threadIdx.x;
    if (i < N_NODES) dinv[i] = rsqrtf((float)(counts[i] + 1));  // +1 self-loop
}

// ---------------- single-block exclusive scan over counts ----------------
__global__ void scan_kernel(const int* __restrict__ counts, int* __restrict__ offsets) {
    int tid = threadIdx.x;
    int lane = tid & 31, wid = tid >> 5;
    __shared__ int wsum[32];
    __shared__ int s_carry;
    if (tid == 0) s_carry = 0;
    __syncthreads();

    for (int base = 0; base < N_NODES; base += 1024) {
        int i = base + tid;
        int v = (i < N_NODES) ? counts[i] : 0;
        int inc = v;
#pragma unroll
        for (int o = 1; o < 32; o <<= 1) {
            int n = __shfl_up_sync(0xffffffffu, inc, o);
            if (lane >= o) inc += n;
        }
        if (lane == 31) wsum[wid] = inc;
        __syncthreads();
        if (wid == 0) {
            int t = wsum[lane];
            int ti = t;
#pragma unroll
            for (int o = 1; o < 32; o <<= 1) {
                int n = __shfl_up_sync(0xffffffffu, ti, o);
                if (lane >= o) ti += n;
            }
            wsum[lane] = ti - t;  // exclusive warp offsets
        }
        __syncthreads();
        int excl = inc - v + wsum[wid] + s_carry;
        if (i < N_NODES) offsets[i] = excl;
        __syncthreads();
        if (tid == 1023) s_carry = excl + v;  // running total
        __syncthreads();
    }
    if (tid == 0) offsets[N_NODES] = s_carry;
}

__global__ void cursor_copy_kernel(const int* __restrict__ offsets, int* cursor) {
    int i = blockIdx.x * blockDim.x + threadIdx.x;
    if (i < N_NODES) cursor[i] = offsets[i];
}

__global__ void fill_kernel(const int* __restrict__ src, const int* __restrict__ dst,
                            const float* __restrict__ dinv,
                            int* cursor, int* __restrict__ csr_src, float* __restrict__ csr_w) {
    int e = blockIdx.x * blockDim.x + threadIdx.x;
    if (e < N_EDGES) {
        int s = src[e], d = dst[e];
        int pos = atomicAdd(&cursor[d], 1);
        csr_src[pos] = s;
        csr_w[pos] = dinv[s] * dinv[d];
    }
}

// ---------------- SGEMM: C[M,256] = A[M,256] @ W[256,256] ----------------
__global__ void sgemm_kernel(const float* __restrict__ A,
                             const float* __restrict__ W,
                             float* __restrict__ C) {
    __shared__ float As[16][65];
    __shared__ float Ws[16][68];

    int tid = threadIdx.x;
    int bm = blockIdx.y * 64;
    int bn = blockIdx.x * 64;
    int tx = tid & 15;
    int ty = tid >> 4;

    int lm  = tid >> 2;
    int lk4 = (tid & 3) * 4;
    int wk  = tid >> 4;
    int wn4 = (tid & 15) * 4;

    int gm = bm + lm;
    bool mval = (gm < N_NODES);
    const float* Arow = A + (size_t)gm * D;

    float acc[4][4];
#pragma unroll
    for (int i = 0; i < 4; i++)
#pragma unroll
        for (int j = 0; j < 4; j++) acc[i][j] = 0.0f;

    for (int k0 = 0; k0 < D; k0 += 16) {
        float4 av = mval ? *(const float4*)(Arow + k0 + lk4)
                         : make_float4(0.f, 0.f, 0.f, 0.f);
        As[lk4 + 0][lm] = av.x;
        As[lk4 + 1][lm] = av.y;
        As[lk4 + 2][lm] = av.z;
        As[lk4 + 3][lm] = av.w;

        float4 wv = *(const float4*)(W + (size_t)(k0 + wk) * D + bn + wn4);
        *(float4*)&Ws[wk][wn4] = wv;

        __syncthreads();
#pragma unroll
        for (int k = 0; k < 16; k++) {
            float a0 = As[k][ty * 4 + 0];
            float a1 = As[k][ty * 4 + 1];
            float a2 = As[k][ty * 4 + 2];
            float a3 = As[k][ty * 4 + 3];
            float4 b4 = *(const float4*)&Ws[k][tx * 4];
            acc[0][0] += a0 * b4.x; acc[0][1] += a0 * b4.y; acc[0][2] += a0 * b4.z; acc[0][3] += a0 * b4.w;
            acc[1][0] += a1 * b4.x; acc[1][1] += a1 * b4.y; acc[1][2] += a1 * b4.z; acc[1][3] += a1 * b4.w;
            acc[2][0] += a2 * b4.x; acc[2][1] += a2 * b4.y; acc[2][2] += a2 * b4.z; acc[2][3] += a2 * b4.w;
            acc[3][0] += a3 * b4.x; acc[3][1] += a3 * b4.y; acc[3][2] += a3 * b4.z; acc[3][3] += a3 * b4.w;
        }
        __syncthreads();
    }

#pragma unroll
    for (int i = 0; i < 4; i++) {
        int r = bm + ty * 4 + i;
        if (r < N_NODES) {
            float4 v = make_float4(acc[i][0], acc[i][1], acc[i][2], acc[i][3]);
            *(float4*)(C + (size_t)r * D + bn + tx * 4) = v;
        }
    }
}

// ---------------- fused CSR aggregation + bias + LayerNorm + ReLU ----------------
// one warp per node, 8 warps per block
__global__ void agg_ln_kernel(const float* __restrict__ h,
                              const int* __restrict__ offsets,
                              const int* __restrict__ csr_src,
                              const float* __restrict__ csr_w,
                              const float* __restrict__ dinv,
                              const float* __restrict__ bias,
                              const float* __restrict__ lw,
                              const float* __restrict__ lb,
                              float* __restrict__ out) {
    int row = blockIdx.x * 8 + (threadIdx.x >> 5);
    int lane = threadIdx.x & 31;
    if (row >= N_NODES) return;

    // self-loop: h[row] * dinv^2
    float di = dinv[row];
    float sw = di * di;
    const float4* hp = (const float4*)(h + (size_t)row * D);
    float4 s0 = hp[lane], s1 = hp[lane + 32];
    float4 v0 = make_float4(s0.x * sw, s0.y * sw, s0.z * sw, s0.w * sw);
    float4 v1 = make_float4(s1.x * sw, s1.y * sw, s1.z * sw, s1.w * sw);

    int e0 = offsets[row];
    int e1 = offsets[row + 1];
    int e = e0;
    for (; e + 2 <= e1; e += 2) {
        int  sA = csr_src[e],   sB = csr_src[e + 1];
        float wA = csr_w[e],    wB = csr_w[e + 1];
        const float4* pA = (const float4*)(h + (size_t)sA * D);
        const float4* pB = (const float4*)(h + (size_t)sB * D);
        float4 a0 = pA[lane], a1 = pA[lane + 32];
        float4 b0 = pB[lane], b1 = pB[lane + 32];
        v0.x += a0.x * wA; v0.y += a0.y * wA; v0.z += a0.z * wA; v0.w += a0.w * wA;
        v1.x += a1.x * wA; v1.y += a1.y * wA; v1.z += a1.z * wA; v1.w += a1.w * wA;
        v0.x += b0.x * wB; v0.y += b0.y * wB; v0.z += b0.z * wB; v0.w += b0.w * wB;
        v1.x += b1.x * wB; v1.y += b1.y * wB; v1.z += b1.z * wB; v1.w += b1.w * wB;
    }
    if (e < e1) {
        int  sA = csr_src[e];
        float wA = csr_w[e];
        const float4* pA = (const float4*)(h + (size_t)sA * D);
        float4 a0 = pA[lane], a1 = pA[lane + 32];
        v0.x += a0.x * wA; v0.y += a0.y * wA; v0.z += a0.z * wA; v0.w += a0.w * wA;
        v1.x += a1.x * wA; v1.y += a1.y * wA; v1.z += a1.z * wA; v1.w += a1.w * wA;
    }

    // + bias
    const float4* bp = (const float4*)bias;
    float4 b0 = bp[lane], b1 = bp[lane + 32];
    v0.x += b0.x; v0.y += b0.y; v0.z += b0.z; v0.w += b0.w;
    v1.x += b1.x; v1.y += b1.y; v1.z += b1.z; v1.w += b1.w;

    // LayerNorm
    float s = v0.x + v0.y + v0.z + v0.w + v1.x + v1.y + v1.z + v1.w;
#pragma unroll
    for (int o = 16; o > 0; o >>= 1) s += __shfl_xor_sync(0xffffffffu, s, o);
    float mu = s * (1.0f / D);

    v0.x -= mu; v0.y -= mu; v0.z -= mu; v0.w -= mu;
    v1.x -= mu; v1.y -= mu; v1.z -= mu; v1.w -= mu;
    float q = v0.x*v0.x + v0.y*v0.y + v0.z*v0.z + v0.w*v0.w
            + v1.x*v1.x + v1.y*v1.y + v1.z*v1.z + v1.w*v1.w;
#pragma unroll
    for (int o = 16; o > 0; o >>= 1) q += __shfl_xor_sync(0xffffffffu, q, o);
    float inv = rsqrtf(q * (1.0f / D) + LN_EPS);

    const float4* wp = (const float4*)lw;
    const float4* lp = (const float4*)lb;
    float4 w0 = wp[lane], w1 = wp[lane + 32];
    float4 l0 = lp[lane], l1 = lp[lane + 32];

    float4 o0, o1;
    o0.x = fmaxf(v0.x * inv * w0.x + l0.x, 0.f);
    o0.y = fmaxf(v0.y * inv * w0.y + l0.y, 0.f);
    o0.z = fmaxf(v0.z * inv * w0.z + l0.z, 0.f);
    o0.w = fmaxf(v0.w * inv * w0.w + l0.w, 0.f);
    o1.x = fmaxf(v1.x * inv * w1.x + l1.x, 0.f);
    o1.y = fmaxf(v1.y * inv * w1.y + l1.y, 0.f);
    o1.z = fmaxf(v1.z * inv * w1.z + l1.z, 0.f);
    o1.w = fmaxf(v1.w * inv * w1.w + l1.w, 0.f);

    float4* op = (float4*)(out + (size_t)row * D);
    op[lane] = o0;
    op[lane + 32] = o1;
}

// ---------------- fused pool + head (batch is sorted) ----------------
__device__ __forceinline__ int lower_bound_dev(const int* a, int n, int key) {
    int lo = 0, hi = n;
    while (lo < hi) {
        int mid = (lo + hi) >> 1;
        if (a[mid] < key) lo = mid + 1; else hi = mid;
    }
    return lo;
}

__global__ void pool_head_kernel(const int* __restrict__ batch,
                                 const float* __restrict__ h,
                                 const float* __restrict__ linW,
                                 const float* __restrict__ linb,
                                 float* __restrict__ out) {
    __shared__ float row[D];
    __shared__ int s_start, s_end;
    int g = blockIdx.x;
    int c = threadIdx.x;
    if (c == 0) {
        s_start = lower_bound_dev(batch, N_NODES, g);
        s_end   = lower_bound_dev(batch, N_NODES, g + 1);
    }
    __syncthreads();
    int start = s_start, end = s_end;
    float sum = 0.0f;
    for (int n = start; n < end; n++) sum += h[(size_t)n * D + c];
    float cnt = (float)(end - start);
    row[c] = sum / fmaxf(cnt, 1.0f);
    __syncthreads();
    if (c < NC) {
        float acc = linb[c];
#pragma unroll 8
        for (int k = 0; k < D; k++) acc += row[k] * linW[k * NC + c];
        out[g * NC + c] = acc;
    }
}

// ---------------- launch ----------------
extern "C" void kernel_launch(void* const* d_in, const int* in_sizes, int n_in,
                              void* d_out, int out_size) {
    const float* x     = (const float*)d_in[0];
    const int*   ei    = (const int*)d_in[1];   // [2, E]
    const int*   batch = (const int*)d_in[2];
    const float* W1    = (const float*)d_in[3];
    const float* b1    = (const float*)d_in[4];
    const float* W2    = (const float*)d_in[5];
    const float* b2    = (const float*)d_in[6];
    const float* ln1w  = (const float*)d_in[7];
    const float* ln1b  = (const float*)d_in[8];
    const float* ln2w  = (const float*)d_in[9];
    const float* ln2b  = (const float*)d_in[10];
    const float* linW  = (const float*)d_in[11];
    const float* linb  = (const float*)d_in[12];
    float* out = (float*)d_out;

    const int* src = ei;
    const int* dst = ei + N_EDGES;

    float *A, *B, *dinv, *csr_w;
    int *counts, *offsets, *cursor, *csr_src;
    cudaGetSymbolAddress((void**)&A,       g_A);
    cudaGetSymbolAddress((void**)&B,       g_B);
    cudaGetSymbolAddress((void**)&dinv,    g_dinv);
    cudaGetSymbolAddress((void**)&counts,  g_counts);
    cudaGetSymbolAddress((void**)&offsets, g_offsets);
    cudaGetSymbolAddress((void**)&cursor,  g_cursor);
    cudaGetSymbolAddress((void**)&csr_src, g_csr_src);
    cudaGetSymbolAddress((void**)&csr_w,   g_csr_w);

    // CSR build
    count_zero_kernel<<<(N_NODES + 255) / 256, 256>>>(counts);
    deg_count_kernel<<<(N_EDGES + 255) / 256, 256>>>(dst, counts);
    dinv_kernel<<<(N_NODES + 255) / 256, 256>>>(counts, dinv);
    scan_kernel<<<1, 1024>>>(counts, offsets);
    cursor_copy_kernel<<<(N_NODES + 255) / 256, 256>>>(offsets, cursor);
    fill_kernel<<<(N_EDGES + 255) / 256, 256>>>(src, dst, dinv, cursor, csr_src, csr_w);

    dim3 ggrid(D / 64, (N_NODES + 63) / 64);

    // layer 1
    sgemm_kernel<<<ggrid, 256>>>(x, W1, A);
    agg_ln_kernel<<<(N_NODES + 7) / 8, 256>>>(A, offsets, csr_src, csr_w, dinv,
                                              b1, ln1w, ln1b, B);
    // layer 2
    sgemm_kernel<<<ggrid, 256>>>(B, W2, A);
    agg_ln_kernel<<<(N_NODES + 7) / 8, 256>>>(A, offsets, csr_src, csr_w, dinv,
                                              b2, ln2w, ln2b, B);

    // pool + head
    pool_head_kernel<<<NG, D>>>(batch, B, linW, linb, out);
}

// round 7
// speedup vs baseline: 3.0527x; 1.2363x over previous
#include <cuda_runtime.h>
#include <math.h>

#define N_NODES 50000
#define N_EDGES 800000
#define D 256
#define NG 512
#define NC 10
#define LN_EPS 1e-5f

#define SCAN_BLK 512
#define SCAN_NB ((N_NODES + SCAN_BLK - 1) / SCAN_BLK)   // 98

// Scratch (device globals; no allocation allowed)
__device__ float g_A[N_NODES * D];
__device__ float g_B[N_NODES * D];
__device__ float g_dinv[N_NODES];
__device__ int   g_counts[N_NODES];
__device__ int   g_offsets[N_NODES + 1];
__device__ int   g_cursor[N_NODES];
__device__ int   g_bsums[SCAN_NB];
__device__ int   g_csr_src[N_EDGES];
__device__ float g_csr_w[N_EDGES];

// ---------------- packed f32x2 helpers ----------------
#define FMA2(c, a, b) \
    asm("fma.rn.f32x2 %0, %1, %2, %0;" : "+l"(c) : "l"(a), "l"(b))
#define BCAST2(d, f) \
    asm("mov.b64 %0, {%1, %1};" : "=l"(d) : "f"(f))

// ---------------- degree ----------------
__global__ void count_zero_kernel(int* counts) {
    int i = blockIdx.x * blockDim.x + threadIdx.x;
    if (i < N_NODES) counts[i] = 0;
}

__global__ void deg_count_kernel(const int* __restrict__ dst, int* counts) {
    int e = blockIdx.x * blockDim.x + threadIdx.x;
    if (e < N_EDGES) atomicAdd(&counts[dst[e]], 1);
}

// ---------------- parallel scan (3 stages) ----------------
__global__ void scan_blocksum_kernel(const int* __restrict__ counts, int* __restrict__ bsums) {
    int t = threadIdx.x;
    int i = blockIdx.x * SCAN_BLK + t;
    int v = (i < N_NODES) ? counts[i] : 0;
#pragma unroll
    for (int o = 16; o > 0; o >>= 1) v += __shfl_xor_sync(0xffffffffu, v, o);
    __shared__ int ws[SCAN_BLK / 32];
    if ((t & 31) == 0) ws[t >> 5] = v;
    __syncthreads();
    if (t == 0) {
        int s = 0;
#pragma unroll
        for (int w = 0; w < SCAN_BLK / 32; w++) s += ws[w];
        bsums[blockIdx.x] = s;
    }
}

__global__ void scan_sums_kernel(int* bsums) {   // exclusive scan, 128 threads, NB<=128
    int t = threadIdx.x;
    int lane = t & 31, w = t >> 5;
    int v = (t < SCAN_NB) ? bsums[t] : 0;
    int inc = v;
#pragma unroll
    for (int o = 1; o < 32; o <<= 1) {
        int n = __shfl_up_sync(0xffffffffu, inc, o);
        if (lane >= o) inc += n;
    }
    __shared__ int ws[4];
    if (lane == 31) ws[w] = inc;
    __syncthreads();
    int add = 0;
    for (int k = 0; k < w; k++) add += ws[k];
    if (t < SCAN_NB) bsums[t] = inc - v + add;
}

// local scan + write offsets, cursor, dinv
__global__ void scan_local_kernel(const int* __restrict__ counts,
                                  const int* __restrict__ bsums,
                                  int* __restrict__ offsets,
                                  int* __restrict__ cursor,
                                  float* __restrict__ dinv) {
    int t = threadIdx.x;
    int lane = t & 31, w = t >> 5;
    int i = blockIdx.x * SCAN_BLK + t;
    int v = (i < N_NODES) ? counts[i] : 0;
    int inc = v;
#pragma unroll
    for (int o = 1; o < 32; o <<= 1) {
        int n = __shfl_up_sync(0xffffffffu, inc, o);
        if (lane >= o) inc += n;
    }
    __shared__ int ws[SCAN_BLK / 32];
    if (lane == 31) ws[w] = inc;
    __syncthreads();
    int add = bsums[blockIdx.x];
    for (int k = 0; k < w; k++) add += ws[k];
    int excl = inc - v + add;
    if (i < N_NODES) {
        offsets[i] = excl;
        cursor[i] = excl;
        dinv[i] = rsqrtf((float)(v + 1));
        if (i == N_NODES - 1) offsets[N_NODES] = excl + v;
    }
}

__global__ void fill_kernel(const int* __restrict__ src, const int* __restrict__ dst,
                            const float* __restrict__ dinv,
                            int* cursor, int* __restrict__ csr_src, float* __restrict__ csr_w) {
    int e = blockIdx.x * blockDim.x + threadIdx.x;
    if (e < N_EDGES) {
        int s = src[e], d = dst[e];
        int pos = atomicAdd(&cursor[d], 1);
        csr_src[pos] = s;
        csr_w[pos] = dinv[s] * dinv[d];
    }
}

// ---------------- SGEMM with packed f32x2: C[M,256] = A[M,256] @ W[256,256] ----
// 128x128 tile, BK=16, 256 threads, 8x8 micro-tile as 32 fma.f32x2 per k.
#define TM 128
#define TN 128
#define BK 16

__global__ __launch_bounds__(256)
void sgemm_kernel(const float* __restrict__ A,
                  const float* __restrict__ W,
                  float* __restrict__ C) {
    __shared__ float As[BK][TM + 4];
    __shared__ float Ws[BK][TN + 4];

    int tid = threadIdx.x;
    int bm = blockIdx.y * TM;
    int bn = blockIdx.x * TN;
    int tx = tid & 15;          // n-group
    int ty = tid >> 4;          // m-group

    // A-load: rows lm, lm+64 ; float4 along k
    int lm  = tid >> 2;
    int lk4 = (tid & 3) * 4;
    // W-load: row wk ; float4 at wn4, wn4+64
    int wk  = tid >> 4;
    int wn4 = (tid & 15) * 4;

    int gm0 = bm + lm, gm1 = bm + lm + 64;
    bool m0v = gm0 < N_NODES, m1v = gm1 < N_NODES;
    const float* A0 = A + (size_t)gm0 * D;
    const float* A1 = A + (size_t)gm1 * D;
    const float* Wp = W + (size_t)wk * D + bn;

    unsigned long long acc[8][4];
#pragma unroll
    for (int i = 0; i < 8; i++)
#pragma unroll
        for (int j = 0; j < 4; j++) acc[i][j] = 0ull;

    // prefetch k0 = 0
    float4 ar0 = m0v ? *(const float4*)(A0 + lk4) : make_float4(0.f,0.f,0.f,0.f);
    float4 ar1 = m1v ? *(const float4*)(A1 + lk4) : make_float4(0.f,0.f,0.f,0.f);
    float4 wr0 = *(const float4*)(Wp + wn4);
    float4 wr1 = *(const float4*)(Wp + wn4 + 64);

    for (int k0 = 0; k0 < D; k0 += BK) {
        As[lk4 + 0][lm] = ar0.x;
        As[lk4 + 1][lm] = ar0.y;
        As[lk4 + 2][lm] = ar0.z;
        As[lk4 + 3][lm] = ar0.w;
        As[lk4 + 0][lm + 64] = ar1.x;
        As[lk4 + 1][lm + 64] = ar1.y;
        As[lk4 + 2][lm + 64] = ar1.z;
        As[lk4 + 3][lm + 64] = ar1.w;
        *(float4*)&Ws[wk][wn4]      = wr0;
        *(float4*)&Ws[wk][wn4 + 64] = wr1;
        __syncthreads();

        if (k0 + BK < D) {
            int kn = k0 + BK;
            ar0 = m0v ? *(const float4*)(A0 + kn + lk4) : make_float4(0.f,0.f,0.f,0.f);
            ar1 = m1v ? *(const float4*)(A1 + kn + lk4) : make_float4(0.f,0.f,0.f,0.f);
            wr0 = *(const float4*)(Wp + (size_t)kn * D + wn4);
            wr1 = *(const float4*)(Wp + (size_t)kn * D + wn4 + 64);
        }

#pragma unroll
        for (int k = 0; k < BK; k++) {
            float4 a0 = *(const float4*)&As[k][ty * 4];
            float4 a1 = *(const float4*)&As[k][ty * 4 + 64];
            ulonglong2 bb0 = *(const ulonglong2*)&Ws[k][tx * 4];
            ulonglong2 bb1 = *(const ulonglong2*)&Ws[k][tx * 4 + 64];
            float am[8] = {a0.x, a0.y, a0.z, a0.w, a1.x, a1.y, a1.z, a1.w};
#pragma unroll
            for (int mi = 0; mi < 8; mi++) {
                unsigned long long pa;
                BCAST2(pa, am[mi]);
                FMA2(acc[mi][0], pa, bb0.x);
                FMA2(acc[mi][1], pa, bb0.y);
                FMA2(acc[mi][2], pa, bb1.x);
                FMA2(acc[mi][3], pa, bb1.y);
            }
        }
        __syncthreads();
    }

    // epilogue
#pragma unroll
    for (int mi = 0; mi < 8; mi++) {
        int r = bm + ty * 4 + (mi & 3) + ((mi >> 2) ? 64 : 0);
        if (r < N_NODES) {
            float* Cp = C + (size_t)r * D + bn;
            *(ulonglong2*)(Cp + tx * 4)      = make_ulonglong2(acc[mi][0], acc[mi][1]);
            *(ulonglong2*)(Cp + tx * 4 + 64) = make_ulonglong2(acc[mi][2], acc[mi][3]);
        }
    }
}

// ---------------- fused CSR aggregation + bias + LayerNorm + ReLU ----------------
__global__ void agg_ln_kernel(const float* __restrict__ h,
                              const int* __restrict__ offsets,
                              const int* __restrict__ csr_src,
                              const float* __restrict__ csr_w,
                              const float* __restrict__ dinv,
                              const float* __restrict__ bias,
                              const float* __restrict__ lw,
                              const float* __restrict__ lb,
                              float* __restrict__ out) {
    int row = blockIdx.x * 8 + (threadIdx.x >> 5);
    int lane = threadIdx.x & 31;
    if (row >= N_NODES) return;

    float di = dinv[row];
    float sw = di * di;
    const float4* hp = (const float4*)(h + (size_t)row * D);
    float4 s0 = hp[lane], s1 = hp[lane + 32];
    float4 v0 = make_float4(s0.x * sw, s0.y * sw, s0.z * sw, s0.w * sw);
    float4 v1 = make_float4(s1.x * sw, s1.y * sw, s1.z * sw, s1.w * sw);

    int e0 = offsets[row];
    int e1 = offsets[row + 1];
    int e = e0;
    for (; e + 2 <= e1; e += 2) {
        int  sA = csr_src[e],   sB = csr_src[e + 1];
        float wA = csr_w[e],    wB = csr_w[e + 1];
        const float4* pA = (const float4*)(h + (size_t)sA * D);
        const float4* pB = (const float4*)(h + (size_t)sB * D);
        float4 a0 = pA[lane], a1 = pA[lane + 32];
        float4 b0 = pB[lane], b1 = pB[lane + 32];
        v0.x += a0.x * wA; v0.y += a0.y * wA; v0.z += a0.z * wA; v0.w += a0.w * wA;
        v1.x += a1.x * wA; v1.y += a1.y * wA; v1.z += a1.z * wA; v1.w += a1.w * wA;
        v0.x += b0.x * wB; v0.y += b0.y * wB; v0.z += b0.z * wB; v0.w += b0.w * wB;
        v1.x += b1.x * wB; v1.y += b1.y * wB; v1.z += b1.z * wB; v1.w += b1.w * wB;
    }
    if (e < e1) {
        int  sA = csr_src[e];
        float wA = csr_w[e];
        const float4* pA = (const float4*)(h + (size_t)sA * D);
        float4 a0 = pA[lane], a1 = pA[lane + 32];
        v0.x += a0.x * wA; v0.y += a0.y * wA; v0.z += a0.z * wA; v0.w += a0.w * wA;
        v1.x += a1.x * wA; v1.y += a1.y * wA; v1.z += a1.z * wA; v1.w += a1.w * wA;
    }

    const float4* bp = (const float4*)bias;
    float4 b0 = bp[lane], b1 = bp[lane + 32];
    v0.x += b0.x; v0.y += b0.y; v0.z += b0.z; v0.w += b0.w;
    v1.x += b1.x; v1.y += b1.y; v1.z += b1.z; v1.w += b1.w;

    float s = v0.x + v0.y + v0.z + v0.w + v1.x + v1.y + v1.z + v1.w;
#pragma unroll
    for (int o = 16; o > 0; o >>= 1) s += __shfl_xor_sync(0xffffffffu, s, o);
    float mu = s * (1.0f / D);

    v0.x -= mu; v0.y -= mu; v0.z -= mu; v0.w -= mu;
    v1.x -= mu; v1.y -= mu; v1.z -= mu; v1.w -= mu;
    float q = v0.x*v0.x + v0.y*v0.y + v0.z*v0.z + v0.w*v0.w
            + v1.x*v1.x + v1.y*v1.y + v1.z*v1.z + v1.w*v1.w;
#pragma unroll
    for (int o = 16; o > 0; o >>= 1) q += __shfl_xor_sync(0xffffffffu, q, o);
    float inv = rsqrtf(q * (1.0f / D) + LN_EPS);

    const float4* wp = (const float4*)lw;
    const float4* lp = (const float4*)lb;
    float4 w0 = wp[lane], w1 = wp[lane + 32];
    float4 l0 = lp[lane], l1 = lp[lane + 32];

    float4 o0, o1;
    o0.x = fmaxf(v0.x * inv * w0.x + l0.x, 0.f);
    o0.y = fmaxf(v0.y * inv * w0.y + l0.y, 0.f);
    o0.z = fmaxf(v0.z * inv * w0.z + l0.z, 0.f);
    o0.w = fmaxf(v0.w * inv * w0.w + l0.w, 0.f);
    o1.x = fmaxf(v1.x * inv * w1.x + l1.x, 0.f);
    o1.y = fmaxf(v1.y * inv * w1.y + l1.y, 0.f);
    o1.z = fmaxf(v1.z * inv * w1.z + l1.z, 0.f);
    o1.w = fmaxf(v1.w * inv * w1.w + l1.w, 0.f);

    float4* op = (float4*)(out + (size_t)row * D);
    op[lane] = o0;
    op[lane + 32] = o1;
}

// ---------------- fused pool + head (batch is sorted) ----------------
__device__ __forceinline__ int lower_bound_dev(const int* a, int n, int key) {
    int lo = 0, hi = n;
    while (lo < hi) {
        int mid = (lo + hi) >> 1;
        if (a[mid] < key) lo = mid + 1; else hi = mid;
    }
    return lo;
}

__global__ void pool_head_kernel(const int* __restrict__ batch,
                                 const float* __restrict__ h,
                                 const float* __restrict__ linW,
                                 const float* __restrict__ linb,
                                 float* __restrict__ out) {
    __shared__ float row[D];
    __shared__ int s_start, s_end;
    int g = blockIdx.x;
    int c = threadIdx.x;
    if (c == 0) {
        s_start = lower_bound_dev(batch, N_NODES, g);
        s_end   = lower_bound_dev(batch, N_NODES, g + 1);
    }
    __syncthreads();
    int start = s_start, end = s_end;
    float sum = 0.0f;
    for (int n = start; n < end; n++) sum += h[(size_t)n * D + c];
    float cnt = (float)(end - start);
    row[c] = sum / fmaxf(cnt, 1.0f);
    __syncthreads();
    if (c < NC) {
        float acc = linb[c];
#pragma unroll 8
        for (int k = 0; k < D; k++) acc += row[k] * linW[k * NC + c];
        out[g * NC + c] = acc;
    }
}

// ---------------- launch ----------------
extern "C" void kernel_launch(void* const* d_in, const int* in_sizes, int n_in,
                              void* d_out, int out_size) {
    const float* x     = (const float*)d_in[0];
    const int*   ei    = (const int*)d_in[1];
    const int*   batch = (const int*)d_in[2];
    const float* W1    = (const float*)d_in[3];
    const float* b1    = (const float*)d_in[4];
    const float* W2    = (const float*)d_in[5];
    const float* b2    = (const float*)d_in[6];
    const float* ln1w  = (const float*)d_in[7];
    const float* ln1b  = (const float*)d_in[8];
    const float* ln2w  = (const float*)d_in[9];
    const float* ln2b  = (const float*)d_in[10];
    const float* linW  = (const float*)d_in[11];
    const float* linb  = (const float*)d_in[12];
    float* out = (float*)d_out;

    const int* src = ei;
    const int* dst = ei + N_EDGES;

    float *A, *B, *dinv, *csr_w;
    int *counts, *offsets, *cursor, *csr_src, *bsums;
    cudaGetSymbolAddress((void**)&A,       g_A);
    cudaGetSymbolAddress((void**)&B,       g_B);
    cudaGetSymbolAddress((void**)&dinv,    g_dinv);
    cudaGetSymbolAddress((void**)&counts,  g_counts);
    cudaGetSymbolAddress((void**)&offsets, g_offsets);
    cudaGetSymbolAddress((void**)&cursor,  g_cursor);
    cudaGetSymbolAddress((void**)&bsums,   g_bsums);
    cudaGetSymbolAddress((void**)&csr_src, g_csr_src);
    cudaGetSymbolAddress((void**)&csr_w,   g_csr_w);

    // CSR build
    count_zero_kernel<<<(N_NODES + 255) / 256, 256>>>(counts);
    deg_count_kernel<<<(N_EDGES + 255) / 256, 256>>>(dst, counts);
    scan_blocksum_kernel<<<SCAN_NB, SCAN_BLK>>>(counts, bsums);
    scan_sums_kernel<<<1, 128>>>(bsums);
    scan_local_kernel<<<SCAN_NB, SCAN_BLK>>>(counts, bsums, offsets, cursor, dinv);
    fill_kernel<<<(N_EDGES + 255) / 256, 256>>>(src, dst, dinv, cursor, csr_src, csr_w);

    dim3 ggrid(D / TN, (N_NODES + TM - 1) / TM);

    // layer 1
    sgemm_kernel<<<ggrid, 256>>>(x, W1, A);
    agg_ln_kernel<<<(N_NODES + 7) / 8, 256>>>(A, offsets, csr_src, csr_w, dinv,
                                              b1, ln1w, ln1b, B);
    // layer 2
    sgemm_kernel<<<ggrid, 256>>>(B, W2, A);
    agg_ln_kernel<<<(N_NODES + 7) / 8, 256>>>(A, offsets, csr_src, csr_w, dinv,
                                              b2, ln2w, ln2b, B);

    // pool + head
    pool_head_kernel<<<NG, D>>>(batch, B, linW, linb, out);
}